// round 6
// baseline (speedup 1.0000x reference)
#include <cuda_runtime.h>
#include <math.h>
#include <stdint.h>

#define B_  2
#define T_  2048
#define C_  2048
#define H_  16
#define KV_ 4
#define D_  128
#define REP_ 4
#define KDIM 2048

// Scratch (allocation-free rule: __device__ globals)
__device__ float g_q[B_ * H_ * T_ * D_];     // [B,H,T,D] q (pre/post rope)
__device__ float g_attn[B_ * T_ * H_ * D_];  // [B,T,H*D] attention output rows

// ---------------------------------------------------------------------------
// tf32 helpers
// ---------------------------------------------------------------------------
__device__ __forceinline__ uint32_t f2tf32(float f) {
    uint32_t u;
    asm("cvt.rna.tf32.f32 %0, %1;" : "=r"(u) : "f"(f));
    return u;
}

__device__ __forceinline__ void mma_tf32(float c[4],
                                         uint32_t a0, uint32_t a1, uint32_t a2, uint32_t a3,
                                         uint32_t b0, uint32_t b1) {
    asm volatile(
        "mma.sync.aligned.m16n8k8.row.col.f32.tf32.tf32.f32 "
        "{%0,%1,%2,%3}, {%4,%5,%6,%7}, {%8,%9}, {%0,%1,%2,%3};"
        : "+f"(c[0]), "+f"(c[1]), "+f"(c[2]), "+f"(c[3])
        : "r"(a0), "r"(a1), "r"(a2), "r"(a3), "r"(b0), "r"(b1));
}

// ---------------------------------------------------------------------------
// Pipelined tf32 GEMM body: out = A[M,2048] @ W[2048,N] (+bias)
// Register-prefetch mainloop: LDG(k0+16) issues before MMA(k0).
// mode 0: row-major out[M,N]; mode 1: scatter [B, N/128 heads, T, 128].
// ---------------------------------------------------------------------------
#define SA 20
#define SB 136

__device__ __forceinline__ void gemm_body(
    const float* __restrict__ A, const float* __restrict__ W,
    const float* __restrict__ bias, float* __restrict__ out,
    int N, int mode, int m0, int n0)
{
    __shared__ uint32_t As[128 * SA];
    __shared__ uint32_t Bs[16 * SB];

    const int tid  = threadIdx.x;
    const int wid  = tid >> 5;
    const int lane = tid & 31;
    const int g = lane >> 2;
    const int t = lane & 3;
    const int warp_m = (wid & 3) * 32;
    const int warp_n = (wid >> 2) * 64;

    float acc[2][8][4];
#pragma unroll
    for (int mt = 0; mt < 2; mt++)
#pragma unroll
        for (int nt = 0; nt < 8; nt++)
#pragma unroll
            for (int i = 0; i < 4; i++) acc[mt][nt][i] = 0.0f;

    const int aRow0 = tid >> 2;
    const int aCol  = (tid & 3) * 4;
    const int bRow0 = tid >> 5;
    const int bCol  = (tid & 31) * 4;

    const float* pa0 = A + (size_t)(m0 + aRow0) * KDIM + aCol;
    const float* pa1 = A + (size_t)(m0 + aRow0 + 64) * KDIM + aCol;
    const float* pb0 = W + (size_t)bRow0 * N + n0 + bCol;
    const float* pb1 = W + (size_t)(bRow0 + 8) * N + n0 + bCol;

    float4 av0 = *(const float4*)pa0;
    float4 av1 = *(const float4*)pa1;
    float4 bv0 = *(const float4*)pb0;
    float4 bv1 = *(const float4*)pb1;

    for (int k0 = 0; k0 < KDIM; k0 += 16) {
        __syncthreads();
        {
            uint32_t* qa0 = &As[aRow0 * SA + aCol];
            qa0[0] = f2tf32(av0.x); qa0[1] = f2tf32(av0.y);
            qa0[2] = f2tf32(av0.z); qa0[3] = f2tf32(av0.w);
            uint32_t* qa1 = &As[(aRow0 + 64) * SA + aCol];
            qa1[0] = f2tf32(av1.x); qa1[1] = f2tf32(av1.y);
            qa1[2] = f2tf32(av1.z); qa1[3] = f2tf32(av1.w);
            uint32_t* qb0 = &Bs[bRow0 * SB + bCol];
            qb0[0] = f2tf32(bv0.x); qb0[1] = f2tf32(bv0.y);
            qb0[2] = f2tf32(bv0.z); qb0[3] = f2tf32(bv0.w);
            uint32_t* qb1 = &Bs[(bRow0 + 8) * SB + bCol];
            qb1[0] = f2tf32(bv1.x); qb1[1] = f2tf32(bv1.y);
            qb1[2] = f2tf32(bv1.z); qb1[3] = f2tf32(bv1.w);
        }
        __syncthreads();

        // prefetch next K-slab (latency hidden behind the MMA block below)
        if (k0 + 16 < KDIM) {
            pa0 += 16; pa1 += 16;
            pb0 += (size_t)16 * N; pb1 += (size_t)16 * N;
            av0 = *(const float4*)pa0;
            av1 = *(const float4*)pa1;
            bv0 = *(const float4*)pb0;
            bv1 = *(const float4*)pb1;
        }

#pragma unroll
        for (int kk = 0; kk < 16; kk += 8) {
            uint32_t afr[2][4];
#pragma unroll
            for (int mt = 0; mt < 2; mt++) {
                const int rb = warp_m + mt * 16;
                afr[mt][0] = As[(rb + g)     * SA + kk + t];
                afr[mt][1] = As[(rb + g + 8) * SA + kk + t];
                afr[mt][2] = As[(rb + g)     * SA + kk + t + 4];
                afr[mt][3] = As[(rb + g + 8) * SA + kk + t + 4];
            }
            uint32_t bfr[8][2];
#pragma unroll
            for (int nt = 0; nt < 8; nt++) {
                const int cn = warp_n + nt * 8 + g;
                bfr[nt][0] = Bs[(kk + t)     * SB + cn];
                bfr[nt][1] = Bs[(kk + t + 4) * SB + cn];
            }
#pragma unroll
            for (int mt = 0; mt < 2; mt++)
#pragma unroll
                for (int nt = 0; nt < 8; nt++)
                    mma_tf32(acc[mt][nt],
                             afr[mt][0], afr[mt][1], afr[mt][2], afr[mt][3],
                             bfr[nt][0], bfr[nt][1]);
        }
    }

#pragma unroll
    for (int mt = 0; mt < 2; mt++) {
#pragma unroll
        for (int nt = 0; nt < 8; nt++) {
            const int col = n0 + warp_n + nt * 8 + 2 * t;
            float bx = 0.0f, by = 0.0f;
            if (bias) { bx = bias[col]; by = bias[col + 1]; }
#pragma unroll
            for (int half = 0; half < 2; half++) {
                const int m = m0 + warp_m + mt * 16 + g + half * 8;
                float2 r;
                r.x = acc[mt][nt][half * 2 + 0] + bx;
                r.y = acc[mt][nt][half * 2 + 1] + by;
                if (mode == 0) {
                    *(float2*)&out[(size_t)m * N + col] = r;
                } else {
                    const int b  = m >> 11;
                    const int tt = m & (T_ - 1);
                    const int h  = col >> 7;
                    const int dd = col & 127;
                    *(float2*)&out[((size_t)(b * (N >> 7) + h) * T_ + tt) * D_ + dd] = r;
                }
            }
        }
    }
}

// Fused QKV: grid.x = 24 (0..15 Q tiles, 16..19 K tiles, 20..23 V tiles)
__global__ __launch_bounds__(256, 2) void qkv_gemm(
    const float* __restrict__ x,
    const float* __restrict__ wq, const float* __restrict__ bq,
    const float* __restrict__ wk, const float* __restrict__ bk,
    const float* __restrict__ wv, const float* __restrict__ bv,
    float* __restrict__ out_k, float* __restrict__ out_v)
{
    const int bx = blockIdx.x;
    const float* W; const float* bias; float* out; int N; int n0;
    if (bx < 16)      { W = wq; bias = bq; out = (float*)g_q; N = 2048; n0 = bx * 128; }
    else if (bx < 20) { W = wk; bias = bk; out = out_k; N = 512; n0 = (bx - 16) * 128; }
    else              { W = wv; bias = bv; out = out_v; N = 512; n0 = (bx - 20) * 128; }
    gemm_body(x, W, bias, out, N, 1, blockIdx.y * 128, n0);
}

__global__ __launch_bounds__(256, 2) void oproj_gemm(
    const float* __restrict__ wo, float* __restrict__ out)
{
    gemm_body((const float*)g_attn, wo, nullptr, out, 2048, 0,
              blockIdx.y * 128, blockIdx.x * 128);
}

// ---------------------------------------------------------------------------
// RoPE in place, fused q (g_q) + k (out_k): pair (j, j+64)
// ---------------------------------------------------------------------------
#define PQ (B_ * H_ * T_ * 64)
#define PK (B_ * KV_ * T_ * 64)

__global__ void rope_all(float* __restrict__ out_k)
{
    int idx = blockIdx.x * blockDim.x + threadIdx.x;
    float* x;
    if (idx < PQ) { x = (float*)g_q; }
    else          { x = out_k; idx -= PQ; if (idx >= PK) return; }

    const int j = idx & 63;
    const int t = (idx >> 6) & (T_ - 1);
    const int bh = idx >> 17;

    const float freq = expf(-13.815510557964274f * ((float)j / 64.0f));
    const float theta = (float)t * freq;
    const float s = sinf(theta);
    const float c = cosf(theta);

    float* base = x + ((size_t)bh * T_ + t) * D_;
    const float v1 = base[j];
    const float v2 = base[j + 64];
    base[j]      = c * v1 - s * v2;
    base[j + 64] = c * v2 + s * v1;
}

// ---------------------------------------------------------------------------
// Flash attention with tf32 MMA (unchanged from round 4 pass).
// ---------------------------------------------------------------------------
#define QF_OFF 0
#define KF_OFF 16384
#define VF_OFF 24576
#define PF_OFF 32768
#define FL_SMEM_WORDS 40960   // 160 KB

__global__ __launch_bounds__(256, 1) void flash_mma(
    const float* __restrict__ k, const float* __restrict__ v)
{
    extern __shared__ uint32_t sm[];
    uint32_t* Qf = sm + QF_OFF;
    uint32_t* Kf = sm + KF_OFF;
    uint32_t* Vf = sm + VF_OFF;
    uint32_t* Pf = sm + PF_OFF;

    const int tid = threadIdx.x;
    const int lane = tid & 31;
    const int wid = tid >> 5;
    const int g = lane >> 2;
    const int t = lane & 3;

    const int q0 = (int)(gridDim.x - 1 - blockIdx.x) * 128;
    const int h  = blockIdx.y;
    const int b  = blockIdx.z;
    const int kvh = h >> 2;

    const float* qp = (const float*)g_q + ((size_t)(b * H_ + h) * T_ + q0) * D_;
    const float* kp = k + ((size_t)(b * KV_ + kvh) * T_) * D_;
    const float* vp = v + ((size_t)(b * KV_ + kvh) * T_) * D_;

    {
        const int mrow  = tid >> 1;
        const int dbase = (tid & 1) * 64;
        const int stripe = mrow >> 4;
        const int r  = mrow & 15;
        const int gg = r & 7;
        const int i0 = r >> 3;
        const float* qrow = qp + (size_t)mrow * D_;
#pragma unroll
        for (int it = 0; it < 16; it++) {
            const int d0 = dbase + it * 4;
            float4 q4 = *(const float4*)(qrow + d0);
            float vals[4] = {q4.x, q4.y, q4.z, q4.w};
#pragma unroll
            for (int j = 0; j < 4; j++) {
                const int dd = d0 + j;
                const int c = dd >> 3, u = dd & 7;
                Qf[(((stripe * 16 + c) * 32) + gg * 4 + (u & 3)) * 4 +
                   (i0 | ((u >> 2) << 1))] = f2tf32(vals[j]);
            }
        }
    }

    float acc_o[16][4];
#pragma unroll
    for (int nt = 0; nt < 16; nt++)
#pragma unroll
        for (int i = 0; i < 4; i++) acc_o[nt][i] = 0.0f;

    float m0 = -INFINITY, m1 = -INFINITY, l0 = 0.0f, l1 = 0.0f;
    const float scale = 0.08838834764831845f;

    const int r0 = q0 + wid * 16 + g;
    const int r1 = r0 + 8;
    const int warp_last = q0 + wid * 16 + 15;

    const int ntiles = q0 / 64 + 2;

    const int srow = tid >> 2;
    const int dbv  = (tid & 3) * 32;
    const int ntk = srow >> 3;
    const int gk  = srow & 7;
    const int csV = srow >> 3;
    const int usV = srow & 7;
    const int tsV = usV & 3;
    const int hsV = usV >> 2;

    for (int ti = 0; ti < ntiles; ti++) {
        const int s0 = ti * 64;
        __syncthreads();
        {
            const float* krow = kp + (size_t)(s0 + srow) * D_;
            const float* vrow = vp + (size_t)(s0 + srow) * D_;
#pragma unroll
            for (int it = 0; it < 8; it++) {
                const int d0 = dbv + it * 4;
                float4 k4 = *(const float4*)(krow + d0);
                float4 v4 = *(const float4*)(vrow + d0);
                float kv[4] = {k4.x, k4.y, k4.z, k4.w};
                float vv[4] = {v4.x, v4.y, v4.z, v4.w};
#pragma unroll
                for (int j = 0; j < 4; j++) {
                    const int dd = d0 + j;
                    const int ck = dd >> 3, uk = dd & 7;
                    Kf[((ntk * 16 + ck) * 32 + gk * 4 + (uk & 3)) * 2 + (uk >> 2)] =
                        f2tf32(kv[j]);
                    const int ntv = dd >> 3, gv = dd & 7;
                    Vf[((ntv * 8 + csV) * 32 + gv * 4 + tsV) * 2 + hsV] =
                        f2tf32(vv[j]);
                }
            }
        }
        __syncthreads();

        if (s0 > warp_last) continue;

        float accs[8][4];
#pragma unroll
        for (int nt = 0; nt < 8; nt++)
#pragma unroll
            for (int i = 0; i < 4; i++) accs[nt][i] = 0.0f;

#pragma unroll
        for (int c = 0; c < 16; c++) {
            uint4 a = *(const uint4*)&Qf[((wid * 16 + c) * 32 + lane) * 4];
#pragma unroll
            for (int nt = 0; nt < 8; nt++) {
                uint2 bb = *(const uint2*)&Kf[((nt * 16 + c) * 32 + lane) * 2];
                mma_tf32(accs[nt], a.x, a.y, a.z, a.w, bb.x, bb.y);
            }
        }

        float mx0 = -INFINITY, mx1 = -INFINITY;
#pragma unroll
        for (int nt = 0; nt < 8; nt++) {
            const int c0 = s0 + nt * 8 + 2 * t;
            accs[nt][0] = (c0     <= r0) ? accs[nt][0] * scale : -INFINITY;
            accs[nt][1] = (c0 + 1 <= r0) ? accs[nt][1] * scale : -INFINITY;
            accs[nt][2] = (c0     <= r1) ? accs[nt][2] * scale : -INFINITY;
            accs[nt][3] = (c0 + 1 <= r1) ? accs[nt][3] * scale : -INFINITY;
            mx0 = fmaxf(mx0, fmaxf(accs[nt][0], accs[nt][1]));
            mx1 = fmaxf(mx1, fmaxf(accs[nt][2], accs[nt][3]));
        }
        mx0 = fmaxf(mx0, __shfl_xor_sync(0xffffffffu, mx0, 1));
        mx0 = fmaxf(mx0, __shfl_xor_sync(0xffffffffu, mx0, 2));
        mx1 = fmaxf(mx1, __shfl_xor_sync(0xffffffffu, mx1, 1));
        mx1 = fmaxf(mx1, __shfl_xor_sync(0xffffffffu, mx1, 2));

        const float mn0 = fmaxf(m0, mx0);
        const float mn1 = fmaxf(m1, mx1);
        const float corr0 = __expf(m0 - mn0);
        const float corr1 = __expf(m1 - mn1);
        m0 = mn0; m1 = mn1;

        float s0s = 0.0f, s1s = 0.0f;
#pragma unroll
        for (int nt = 0; nt < 8; nt++) {
            accs[nt][0] = __expf(accs[nt][0] - mn0);
            accs[nt][1] = __expf(accs[nt][1] - mn0);
            accs[nt][2] = __expf(accs[nt][2] - mn1);
            accs[nt][3] = __expf(accs[nt][3] - mn1);
            s0s += accs[nt][0] + accs[nt][1];
            s1s += accs[nt][2] + accs[nt][3];
        }
        s0s += __shfl_xor_sync(0xffffffffu, s0s, 1);
        s0s += __shfl_xor_sync(0xffffffffu, s0s, 2);
        s1s += __shfl_xor_sync(0xffffffffu, s1s, 1);
        s1s += __shfl_xor_sync(0xffffffffu, s1s, 2);
        l0 = l0 * corr0 + s0s;
        l1 = l1 * corr1 + s1s;

#pragma unroll
        for (int nt = 0; nt < 16; nt++) {
            acc_o[nt][0] *= corr0; acc_o[nt][1] *= corr0;
            acc_o[nt][2] *= corr1; acc_o[nt][3] *= corr1;
        }

        __syncwarp();
#pragma unroll
        for (int nt = 0; nt < 8; nt++) {
            const int u0 = 2 * t, u1 = 2 * t + 1;
            const int base = (wid * 8 + nt) * 32 + g * 4;
            Pf[(base + (u0 & 3)) * 4 + ((u0 >> 2) << 1) + 0] = f2tf32(accs[nt][0]);
            Pf[(base + (u0 & 3)) * 4 + ((u0 >> 2) << 1) + 1] = f2tf32(accs[nt][2]);
            Pf[(base + (u1 & 3)) * 4 + ((u1 >> 2) << 1) + 0] = f2tf32(accs[nt][1]);
            Pf[(base + (u1 & 3)) * 4 + ((u1 >> 2) << 1) + 1] = f2tf32(accs[nt][3]);
        }
        __syncwarp();

#pragma unroll
        for (int c = 0; c < 8; c++) {
            uint4 a = *(const uint4*)&Pf[((wid * 8 + c) * 32 + lane) * 4];
#pragma unroll
            for (int nt = 0; nt < 16; nt++) {
                uint2 bb = *(const uint2*)&Vf[((nt * 8 + c) * 32 + lane) * 2];
                mma_tf32(acc_o[nt], a.x, a.y, a.z, a.w, bb.x, bb.y);
            }
        }
    }

    const float inv0 = 1.0f / l0;
    const float inv1 = 1.0f / l1;
    float* o = (float*)g_attn;
    const size_t ro0 = ((size_t)(b * T_ + r0)) * C_ + h * D_;
    const size_t ro1 = ((size_t)(b * T_ + r1)) * C_ + h * D_;
#pragma unroll
    for (int nt = 0; nt < 16; nt++) {
        const int col = nt * 8 + 2 * t;
        float2 w0, w1;
        w0.x = acc_o[nt][0] * inv0; w0.y = acc_o[nt][1] * inv0;
        w1.x = acc_o[nt][2] * inv1; w1.y = acc_o[nt][3] * inv1;
        *(float2*)&o[ro0 + col] = w0;
        *(float2*)&o[ro1 + col] = w1;
    }
}

// ---------------------------------------------------------------------------
extern "C" void kernel_launch(void* const* d_in, const int* in_sizes, int n_in,
                              void* d_out, int out_size)
{
    const float* x  = (const float*)d_in[0];
    const float* wq = (const float*)d_in[1];
    const float* bq = (const float*)d_in[2];
    const float* wk = (const float*)d_in[3];
    const float* bk = (const float*)d_in[4];
    const float* wv = (const float*)d_in[5];
    const float* bv = (const float*)d_in[6];
    const float* wo = (const float*)d_in[7];

    float* out_main = (float*)d_out;                    // [B,T,C]
    float* out_k = out_main + (size_t)B_ * T_ * C_;     // [B,KV,T,D]
    float* out_v = out_k + (size_t)B_ * KV_ * T_ * D_;  // [B,KV,T,D]

    const int M = B_ * T_;  // 4096

    // Fused QKV projection (single launch, 24x32 tiles)
    {
        dim3 g(24, M / 128);
        qkv_gemm<<<g, 256>>>(x, wq, bq, wk, bk, wv, bv, out_k, out_v);
    }

    // RoPE on q (g_q) and k (out_k), fused single launch
    {
        const int total = PQ + PK;
        rope_all<<<(total + 255) / 256, 256>>>(out_k);
    }

    // Flash attention (tf32 MMA)
    {
        const int smem = FL_SMEM_WORDS * (int)sizeof(uint32_t);  // 163840
        cudaFuncSetAttribute(flash_mma,
                             cudaFuncAttributeMaxDynamicSharedMemorySize, smem);
        dim3 g(T_ / 128, H_, B_);
        flash_mma<<<g, 256, smem>>>(out_k, out_v);
    }

    // Output projection
    {
        dim3 go(C_ / 128, M / 128);
        oproj_gemm<<<go, 256>>>(wo, out_main);
    }
}

// round 9
// speedup vs baseline: 1.0839x; 1.0839x over previous
#include <cuda_runtime.h>
#include <math.h>
#include <stdint.h>

#define B_  2
#define T_  2048
#define C_  2048
#define H_  16
#define KV_ 4
#define D_  128
#define REP_ 4
#define KDIM 2048

// Scratch (allocation-free rule: __device__ globals)
__device__ float g_q[B_ * H_ * T_ * D_];     // [B,H,T,D] q (pre/post rope)
__device__ float g_attn[B_ * T_ * H_ * D_];  // [B,T,H*D] attention output rows

// ---------------------------------------------------------------------------
// tf32 helpers
// ---------------------------------------------------------------------------
__device__ __forceinline__ uint32_t f2tf32(float f) {
    uint32_t u;
    asm("cvt.rna.tf32.f32 %0, %1;" : "=r"(u) : "f"(f));
    return u;
}

__device__ __forceinline__ void mma_tf32(float c[4],
                                         uint32_t a0, uint32_t a1, uint32_t a2, uint32_t a3,
                                         uint32_t b0, uint32_t b1) {
    asm volatile(
        "mma.sync.aligned.m16n8k8.row.col.f32.tf32.tf32.f32 "
        "{%0,%1,%2,%3}, {%4,%5,%6,%7}, {%8,%9}, {%0,%1,%2,%3};"
        : "+f"(c[0]), "+f"(c[1]), "+f"(c[2]), "+f"(c[3])
        : "r"(a0), "r"(a1), "r"(a2), "r"(a3), "r"(b0), "r"(b1));
}

// ---------------------------------------------------------------------------
// tf32 GEMM, 64x64 warp tiles: out = A[M,2048] @ W[2048,N] (+bias)
// CTA tile 128x128, 128 threads (4 warps, each 64x64), BK=16,
// register-prefetch pipelined mainloop. 128 B of fragment LDS per MMA
// (vs 192 for 32x64 tiles) -> lower L1 pressure per tensor op.
// mode 0: row-major out[M,N]; mode 1: scatter [B, N/128 heads, T, 128].
// ---------------------------------------------------------------------------
#define SA 20
#define SB 136

__device__ __forceinline__ void gemm_body(
    const float* __restrict__ A, const float* __restrict__ W,
    const float* __restrict__ bias, float* __restrict__ out,
    int N, int mode, int m0, int n0)
{
    __shared__ uint32_t As[128 * SA];
    __shared__ uint32_t Bs[16 * SB];

    const int tid  = threadIdx.x;          // 0..127
    const int wid  = tid >> 5;             // 0..3
    const int lane = tid & 31;
    const int g = lane >> 2;               // 0..7
    const int t = lane & 3;                // 0..3
    const int warp_m = (wid & 1) * 64;
    const int warp_n = (wid >> 1) * 64;

    float acc[4][8][4];
#pragma unroll
    for (int mt = 0; mt < 4; mt++)
#pragma unroll
        for (int nt = 0; nt < 8; nt++)
#pragma unroll
            for (int i = 0; i < 4; i++) acc[mt][nt][i] = 0.0f;

    // A: 128x16 per slab. thread -> rows (tid>>2)+32c, cols (tid&3)*4 (64B segs)
    const int aRow = tid >> 2;             // 0..31
    const int aCol = (tid & 3) * 4;
    // B: 16x128 per slab. thread -> rows (tid>>5)+4c, cols (tid&31)*4 (full rows)
    const int bRow = tid >> 5;             // 0..3
    const int bCol = (tid & 31) * 4;

    const float* pa = A + (size_t)(m0 + aRow) * KDIM + aCol;
    const float* pb = W + (size_t)bRow * N + n0 + bCol;

    float4 av[4], bv[4];
#pragma unroll
    for (int c = 0; c < 4; c++) {
        av[c] = *(const float4*)(pa + (size_t)(32 * c) * KDIM);
        bv[c] = *(const float4*)(pb + (size_t)(4 * c) * N);
    }

    for (int k0 = 0; k0 < KDIM; k0 += 16) {
        __syncthreads();
#pragma unroll
        for (int c = 0; c < 4; c++) {
            uint32_t* qa = &As[(aRow + 32 * c) * SA + aCol];
            qa[0] = f2tf32(av[c].x); qa[1] = f2tf32(av[c].y);
            qa[2] = f2tf32(av[c].z); qa[3] = f2tf32(av[c].w);
            uint32_t* qb = &Bs[(bRow + 4 * c) * SB + bCol];
            qb[0] = f2tf32(bv[c].x); qb[1] = f2tf32(bv[c].y);
            qb[2] = f2tf32(bv[c].z); qb[3] = f2tf32(bv[c].w);
        }
        __syncthreads();

        // prefetch next K-slab (hidden behind the 64 MMAs below)
        if (k0 + 16 < KDIM) {
            pa += 16;
            pb += (size_t)16 * N;
#pragma unroll
            for (int c = 0; c < 4; c++) {
                av[c] = *(const float4*)(pa + (size_t)(32 * c) * KDIM);
                bv[c] = *(const float4*)(pb + (size_t)(4 * c) * N);
            }
        }

#pragma unroll
        for (int kk = 0; kk < 16; kk += 8) {
            uint32_t afr[4][4];
#pragma unroll
            for (int mt = 0; mt < 4; mt++) {
                const int rb = warp_m + mt * 16;
                afr[mt][0] = As[(rb + g)     * SA + kk + t];
                afr[mt][1] = As[(rb + g + 8) * SA + kk + t];
                afr[mt][2] = As[(rb + g)     * SA + kk + t + 4];
                afr[mt][3] = As[(rb + g + 8) * SA + kk + t + 4];
            }
            uint32_t bfr[8][2];
#pragma unroll
            for (int nt = 0; nt < 8; nt++) {
                const int cn = warp_n + nt * 8 + g;
                bfr[nt][0] = Bs[(kk + t)     * SB + cn];
                bfr[nt][1] = Bs[(kk + t + 4) * SB + cn];
            }
#pragma unroll
            for (int mt = 0; mt < 4; mt++)
#pragma unroll
                for (int nt = 0; nt < 8; nt++)
                    mma_tf32(acc[mt][nt],
                             afr[mt][0], afr[mt][1], afr[mt][2], afr[mt][3],
                             bfr[nt][0], bfr[nt][1]);
        }
    }

#pragma unroll
    for (int mt = 0; mt < 4; mt++) {
#pragma unroll
        for (int nt = 0; nt < 8; nt++) {
            const int col = n0 + warp_n + nt * 8 + 2 * t;
            float bx = 0.0f, by = 0.0f;
            if (bias) { bx = bias[col]; by = bias[col + 1]; }
#pragma unroll
            for (int half = 0; half < 2; half++) {
                const int m = m0 + warp_m + mt * 16 + g + half * 8;
                float2 r;
                r.x = acc[mt][nt][half * 2 + 0] + bx;
                r.y = acc[mt][nt][half * 2 + 1] + by;
                if (mode == 0) {
                    *(float2*)&out[(size_t)m * N + col] = r;
                } else {
                    const int b  = m >> 11;
                    const int tt = m & (T_ - 1);
                    const int h  = col >> 7;
                    const int dd = col & 127;
                    *(float2*)&out[((size_t)(b * (N >> 7) + h) * T_ + tt) * D_ + dd] = r;
                }
            }
        }
    }
}

// Fused QKV: grid.x = 24 (0..15 Q tiles, 16..19 K tiles, 20..23 V tiles)
__global__ __launch_bounds__(128, 2) void qkv_gemm(
    const float* __restrict__ x,
    const float* __restrict__ wq, const float* __restrict__ bq,
    const float* __restrict__ wk, const float* __restrict__ bk,
    const float* __restrict__ wv, const float* __restrict__ bv,
    float* __restrict__ out_k, float* __restrict__ out_v)
{
    const int bx = blockIdx.x;
    const float* W; const float* bias; float* out; int N; int n0;
    if (bx < 16)      { W = wq; bias = bq; out = (float*)g_q; N = 2048; n0 = bx * 128; }
    else if (bx < 20) { W = wk; bias = bk; out = out_k; N = 512; n0 = (bx - 16) * 128; }
    else              { W = wv; bias = bv; out = out_v; N = 512; n0 = (bx - 20) * 128; }
    gemm_body(x, W, bias, out, N, 1, blockIdx.y * 128, n0);
}

__global__ __launch_bounds__(128, 2) void oproj_gemm(
    const float* __restrict__ wo, float* __restrict__ out)
{
    gemm_body((const float*)g_attn, wo, nullptr, out, 2048, 0,
              blockIdx.y * 128, blockIdx.x * 128);
}

// ---------------------------------------------------------------------------
// RoPE in place, fused q (g_q) + k (out_k): pair (j, j+64)
// ---------------------------------------------------------------------------
#define PQ (B_ * H_ * T_ * 64)
#define PK (B_ * KV_ * T_ * 64)

__global__ void rope_all(float* __restrict__ out_k)
{
    int idx = blockIdx.x * blockDim.x + threadIdx.x;
    float* x;
    if (idx < PQ) { x = (float*)g_q; }
    else          { x = out_k; idx -= PQ; if (idx >= PK) return; }

    const int j = idx & 63;
    const int t = (idx >> 6) & (T_ - 1);
    const int bh = idx >> 17;

    const float freq = expf(-13.815510557964274f * ((float)j / 64.0f));
    const float theta = (float)t * freq;
    const float s = sinf(theta);
    const float c = cosf(theta);

    float* base = x + ((size_t)bh * T_ + t) * D_;
    const float v1 = base[j];
    const float v2 = base[j + 64];
    base[j]      = c * v1 - s * v2;
    base[j + 64] = c * v2 + s * v1;
}

// ---------------------------------------------------------------------------
// Flash attention with tf32 MMA (proven r4/r5) — unchanged.
// ---------------------------------------------------------------------------
#define QF_OFF 0
#define KF_OFF 16384
#define VF_OFF 24576
#define PF_OFF 32768
#define FL_SMEM_WORDS 40960   // 160 KB

__global__ __launch_bounds__(256, 1) void flash_mma(
    const float* __restrict__ k, const float* __restrict__ v)
{
    extern __shared__ uint32_t sm[];
    uint32_t* Qf = sm + QF_OFF;
    uint32_t* Kf = sm + KF_OFF;
    uint32_t* Vf = sm + VF_OFF;
    uint32_t* Pf = sm + PF_OFF;

    const int tid = threadIdx.x;
    const int lane = tid & 31;
    const int wid = tid >> 5;
    const int g = lane >> 2;
    const int t = lane & 3;

    const int q0 = (int)(gridDim.x - 1 - blockIdx.x) * 128;
    const int h  = blockIdx.y;
    const int b  = blockIdx.z;
    const int kvh = h >> 2;

    const float* qp = (const float*)g_q + ((size_t)(b * H_ + h) * T_ + q0) * D_;
    const float* kp = k + ((size_t)(b * KV_ + kvh) * T_) * D_;
    const float* vp = v + ((size_t)(b * KV_ + kvh) * T_) * D_;

    {
        const int mrow  = tid >> 1;
        const int dbase = (tid & 1) * 64;
        const int stripe = mrow >> 4;
        const int r  = mrow & 15;
        const int gg = r & 7;
        const int i0 = r >> 3;
        const float* qrow = qp + (size_t)mrow * D_;
#pragma unroll
        for (int it = 0; it < 16; it++) {
            const int d0 = dbase + it * 4;
            float4 q4 = *(const float4*)(qrow + d0);
            float vals[4] = {q4.x, q4.y, q4.z, q4.w};
#pragma unroll
            for (int j = 0; j < 4; j++) {
                const int dd = d0 + j;
                const int c = dd >> 3, u = dd & 7;
                Qf[(((stripe * 16 + c) * 32) + gg * 4 + (u & 3)) * 4 +
                   (i0 | ((u >> 2) << 1))] = f2tf32(vals[j]);
            }
        }
    }

    float acc_o[16][4];
#pragma unroll
    for (int nt = 0; nt < 16; nt++)
#pragma unroll
        for (int i = 0; i < 4; i++) acc_o[nt][i] = 0.0f;

    float m0 = -INFINITY, m1 = -INFINITY, l0 = 0.0f, l1 = 0.0f;
    const float scale = 0.08838834764831845f;

    const int r0 = q0 + wid * 16 + g;
    const int r1 = r0 + 8;
    const int warp_last = q0 + wid * 16 + 15;
    const int ntiles = q0 / 64 + 2;

    const int srow = tid >> 2;
    const int dbv  = (tid & 3) * 32;
    const int ntk = srow >> 3;
    const int gk  = srow & 7;
    const int csV = srow >> 3;
    const int usV = srow & 7;
    const int tsV = usV & 3;
    const int hsV = usV >> 2;

    for (int ti = 0; ti < ntiles; ti++) {
        const int s0 = ti * 64;
        __syncthreads();
        {
            const float* krow = kp + (size_t)(s0 + srow) * D_;
            const float* vrow = vp + (size_t)(s0 + srow) * D_;
#pragma unroll
            for (int it = 0; it < 8; it++) {
                const int d0 = dbv + it * 4;
                float4 k4 = *(const float4*)(krow + d0);
                float4 v4 = *(const float4*)(vrow + d0);
                float kv[4] = {k4.x, k4.y, k4.z, k4.w};
                float vv[4] = {v4.x, v4.y, v4.z, v4.w};
#pragma unroll
                for (int j = 0; j < 4; j++) {
                    const int dd = d0 + j;
                    const int ck = dd >> 3, uk = dd & 7;
                    Kf[((ntk * 16 + ck) * 32 + gk * 4 + (uk & 3)) * 2 + (uk >> 2)] =
                        f2tf32(kv[j]);
                    const int ntv = dd >> 3, gv = dd & 7;
                    Vf[((ntv * 8 + csV) * 32 + gv * 4 + tsV) * 2 + hsV] =
                        f2tf32(vv[j]);
                }
            }
        }
        __syncthreads();

        if (s0 > warp_last) continue;

        float accs[8][4];
#pragma unroll
        for (int nt = 0; nt < 8; nt++)
#pragma unroll
            for (int i = 0; i < 4; i++) accs[nt][i] = 0.0f;

#pragma unroll
        for (int c = 0; c < 16; c++) {
            uint4 a = *(const uint4*)&Qf[((wid * 16 + c) * 32 + lane) * 4];
#pragma unroll
            for (int nt = 0; nt < 8; nt++) {
                uint2 bb = *(const uint2*)&Kf[((nt * 16 + c) * 32 + lane) * 2];
                mma_tf32(accs[nt], a.x, a.y, a.z, a.w, bb.x, bb.y);
            }
        }

        float mx0 = -INFINITY, mx1 = -INFINITY;
#pragma unroll
        for (int nt = 0; nt < 8; nt++) {
            const int c0 = s0 + nt * 8 + 2 * t;
            accs[nt][0] = (c0     <= r0) ? accs[nt][0] * scale : -INFINITY;
            accs[nt][1] = (c0 + 1 <= r0) ? accs[nt][1] * scale : -INFINITY;
            accs[nt][2] = (c0     <= r1) ? accs[nt][2] * scale : -INFINITY;
            accs[nt][3] = (c0 + 1 <= r1) ? accs[nt][3] * scale : -INFINITY;
            mx0 = fmaxf(mx0, fmaxf(accs[nt][0], accs[nt][1]));
            mx1 = fmaxf(mx1, fmaxf(accs[nt][2], accs[nt][3]));
        }
        mx0 = fmaxf(mx0, __shfl_xor_sync(0xffffffffu, mx0, 1));
        mx0 = fmaxf(mx0, __shfl_xor_sync(0xffffffffu, mx0, 2));
        mx1 = fmaxf(mx1, __shfl_xor_sync(0xffffffffu, mx1, 1));
        mx1 = fmaxf(mx1, __shfl_xor_sync(0xffffffffu, mx1, 2));

        const float mn0 = fmaxf(m0, mx0);
        const float mn1 = fmaxf(m1, mx1);
        const float corr0 = __expf(m0 - mn0);
        const float corr1 = __expf(m1 - mn1);
        m0 = mn0; m1 = mn1;

        float s0s = 0.0f, s1s = 0.0f;
#pragma unroll
        for (int nt = 0; nt < 8; nt++) {
            accs[nt][0] = __expf(accs[nt][0] - mn0);
            accs[nt][1] = __expf(accs[nt][1] - mn0);
            accs[nt][2] = __expf(accs[nt][2] - mn1);
            accs[nt][3] = __expf(accs[nt][3] - mn1);
            s0s += accs[nt][0] + accs[nt][1];
            s1s += accs[nt][2] + accs[nt][3];
        }
        s0s += __shfl_xor_sync(0xffffffffu, s0s, 1);
        s0s += __shfl_xor_sync(0xffffffffu, s0s, 2);
        s1s += __shfl_xor_sync(0xffffffffu, s1s, 1);
        s1s += __shfl_xor_sync(0xffffffffu, s1s, 2);
        l0 = l0 * corr0 + s0s;
        l1 = l1 * corr1 + s1s;

#pragma unroll
        for (int nt = 0; nt < 16; nt++) {
            acc_o[nt][0] *= corr0; acc_o[nt][1] *= corr0;
            acc_o[nt][2] *= corr1; acc_o[nt][3] *= corr1;
        }

        __syncwarp();
#pragma unroll
        for (int nt = 0; nt < 8; nt++) {
            const int u0 = 2 * t, u1 = 2 * t + 1;
            const int base = (wid * 8 + nt) * 32 + g * 4;
            Pf[(base + (u0 & 3)) * 4 + ((u0 >> 2) << 1) + 0] = f2tf32(accs[nt][0]);
            Pf[(base + (u0 & 3)) * 4 + ((u0 >> 2) << 1) + 1] = f2tf32(accs[nt][2]);
            Pf[(base + (u1 & 3)) * 4 + ((u1 >> 2) << 1) + 0] = f2tf32(accs[nt][1]);
            Pf[(base + (u1 & 3)) * 4 + ((u1 >> 2) << 1) + 1] = f2tf32(accs[nt][3]);
        }
        __syncwarp();

#pragma unroll
        for (int c = 0; c < 8; c++) {
            uint4 a = *(const uint4*)&Pf[((wid * 8 + c) * 32 + lane) * 4];
#pragma unroll
            for (int nt = 0; nt < 16; nt++) {
                uint2 bb = *(const uint2*)&Vf[((nt * 8 + c) * 32 + lane) * 2];
                mma_tf32(acc_o[nt], a.x, a.y, a.z, a.w, bb.x, bb.y);
            }
        }
    }

    const float inv0 = 1.0f / l0;
    const float inv1 = 1.0f / l1;
    float* o = (float*)g_attn;
    const size_t ro0 = ((size_t)(b * T_ + r0)) * C_ + h * D_;
    const size_t ro1 = ((size_t)(b * T_ + r1)) * C_ + h * D_;
#pragma unroll
    for (int nt = 0; nt < 16; nt++) {
        const int col = nt * 8 + 2 * t;
        float2 w0, w1;
        w0.x = acc_o[nt][0] * inv0; w0.y = acc_o[nt][1] * inv0;
        w1.x = acc_o[nt][2] * inv1; w1.y = acc_o[nt][3] * inv1;
        *(float2*)&o[ro0 + col] = w0;
        *(float2*)&o[ro1 + col] = w1;
    }
}

// ---------------------------------------------------------------------------
extern "C" void kernel_launch(void* const* d_in, const int* in_sizes, int n_in,
                              void* d_out, int out_size)
{
    const float* x  = (const float*)d_in[0];
    const float* wq = (const float*)d_in[1];
    const float* bq = (const float*)d_in[2];
    const float* wk = (const float*)d_in[3];
    const float* bk = (const float*)d_in[4];
    const float* wv = (const float*)d_in[5];
    const float* bv = (const float*)d_in[6];
    const float* wo = (const float*)d_in[7];

    float* out_main = (float*)d_out;                    // [B,T,C]
    float* out_k = out_main + (size_t)B_ * T_ * C_;     // [B,KV,T,D]
    float* out_v = out_k + (size_t)B_ * KV_ * T_ * D_;  // [B,KV,T,D]

    const int M = B_ * T_;  // 4096

    // Fused QKV projection
    {
        dim3 g(24, M / 128);
        qkv_gemm<<<g, 128>>>(x, wq, bq, wk, bk, wv, bv, out_k, out_v);
    }

    // RoPE on q (g_q) and k (out_k), fused single launch
    {
        const int total = PQ + PK;
        rope_all<<<(total + 255) / 256, 256>>>(out_k);
    }

    // Flash attention (tf32 MMA)
    {
        const int smem = FL_SMEM_WORDS * (int)sizeof(uint32_t);  // 163840
        cudaFuncSetAttribute(flash_mma,
                             cudaFuncAttributeMaxDynamicSharedMemorySize, smem);
        dim3 g(T_ / 128, H_, B_);
        flash_mma<<<g, 256, smem>>>(out_k, out_v);
    }

    // Output projection
    {
        dim3 go(C_ / 128, M / 128);
        oproj_gemm<<<go, 128>>>(wo, out_main);
    }
}